// round 6
// baseline (speedup 1.0000x reference)
#include <cuda_runtime.h>
#include <cstdint>

// Problem shape (fixed):
//   x:      [8192, 4096] f32 (A, row-major)      d_in[0]
//   weight: [4096, 4096] f32 (W, row-major)      d_in[1]
//   bias:   [4096] f32                           d_in[2]
//   sw:     [262144] f32                         d_in[3]
//   idx:    [2, 262144] i32 (rows, cols)         d_in[4]
//   out = x @ (W + scatter)^T + bias   [8192, 4096] f32
//
// tcgen05 unavailable (toolchain lowers via plain compute_103 PTX target);
// arch-portable mma.sync m16n8k8 tf32 on the tensor pipe.
//
// Scratch copies of x and W' are tf32-rounded AND k-interleaved (within each
// 16-k group, pos p = (k%4)*4 + k/4) so one 16B smem chunk = {k,k+4,k+8,k+12}
// = the A (or B) register operands of TWO m16n8k8 MMAs. Fragment loads are
// conflict-free LDS.128 (4x fewer shared-memory issues than LDS.32).
//
// IMPORTANT: __device__ globals are only referenced from device code (passing
// them as host-side kernel args silently uses the host shadow address).

#define M_DIM 8192
#define N_DIM 4096
#define K_DIM 4096

#define BM 128
#define BN 256
#define BK 32
#define STAGES 4
#define NKT (K_DIM / BK)        // 128

#define A_STAGE_BYTES (BM * BK * 4)     // 16384
#define B_STAGE_BYTES (BN * BK * 4)     // 32768
#define SMEM_TOTAL (STAGES * (A_STAGE_BYTES + B_STAGE_BYTES))   // 196608

// row-swizzle for 16B chunks (rows r, r+1 differ in bit2 of the perm so each
// 8-lane LDS.128 phase hits 8 distinct 16B bank groups)
#define PERM(r) ((((r) & 1) << 2) | (((r) >> 1) & 3))

// Device scratch (allocation-free): tf32-rounded + k-interleaved copies
__device__ float g_wt[(size_t)N_DIM * K_DIM];
__device__ float g_x[(size_t)M_DIM * K_DIM];

// ---------------------------------------------------------------------------
// helpers
// ---------------------------------------------------------------------------
__device__ __forceinline__ uint32_t smem_u32(const void* p) {
    uint32_t a;
    asm("{ .reg .u64 t; cvta.to.shared.u64 t, %1; cvt.u32.u64 %0, t; }"
        : "=r"(a) : "l"(p));
    return a;
}

__device__ __forceinline__ float round_tf32(float f) {
    uint32_t u;
    asm("cvt.rna.tf32.f32 %0, %1;" : "=r"(u) : "f"(f));
    return __uint_as_float(u);
}

#define CP_ASYNC16(dst, src) \
    asm volatile("cp.async.cg.shared.global [%0], [%1], 16;" :: "r"(dst), "l"(src))
#define CP_COMMIT() asm volatile("cp.async.commit_group;" ::: "memory")
#define CP_WAIT2()  asm volatile("cp.async.wait_group 2;" ::: "memory")

__device__ __forceinline__ void mma_tf32(float& c0, float& c1, float& c2, float& c3,
                                         uint32_t a0, uint32_t a1, uint32_t a2, uint32_t a3,
                                         uint32_t b0, uint32_t b1) {
    asm volatile(
        "mma.sync.aligned.m16n8k8.row.col.f32.tf32.tf32.f32 "
        "{%0,%1,%2,%3}, {%4,%5,%6,%7}, {%8,%9}, {%0,%1,%2,%3};"
        : "+f"(c0), "+f"(c1), "+f"(c2), "+f"(c3)
        : "r"(a0), "r"(a1), "r"(a2), "r"(a3), "r"(b0), "r"(b1));
}

// ---------------------------------------------------------------------------
// Prologue: round to tf32 + k-interleave (device-global destinations
// referenced from device code, NOT passed from host)
// ---------------------------------------------------------------------------
__device__ __forceinline__ void round_perm_body(const float4* __restrict__ src4,
                                                float4* __restrict__ dst4,
                                                size_t g) {
    float4 a = src4[g * 4 + 0];   // k 0..3
    float4 b = src4[g * 4 + 1];   // k 4..7
    float4 c = src4[g * 4 + 2];   // k 8..11
    float4 d = src4[g * 4 + 3];   // k 12..15
    float4 o0, o1, o2, o3;
    o0.x = round_tf32(a.x); o0.y = round_tf32(b.x); o0.z = round_tf32(c.x); o0.w = round_tf32(d.x);
    o1.x = round_tf32(a.y); o1.y = round_tf32(b.y); o1.z = round_tf32(c.y); o1.w = round_tf32(d.y);
    o2.x = round_tf32(a.z); o2.y = round_tf32(b.z); o2.z = round_tf32(c.z); o2.w = round_tf32(d.z);
    o3.x = round_tf32(a.w); o3.y = round_tf32(b.w); o3.z = round_tf32(c.w); o3.w = round_tf32(d.w);
    dst4[g * 4 + 0] = o0;
    dst4[g * 4 + 1] = o1;
    dst4[g * 4 + 2] = o2;
    dst4[g * 4 + 3] = o3;
}

__global__ void round_perm_w_kernel(const float4* __restrict__ src4) {
    size_t g = (size_t)blockIdx.x * blockDim.x + threadIdx.x;
    round_perm_body(src4, reinterpret_cast<float4*>(g_wt), g);
}

__global__ void round_perm_x_kernel(const float4* __restrict__ src4) {
    size_t g = (size_t)blockIdx.x * blockDim.x + threadIdx.x;
    round_perm_body(src4, reinterpret_cast<float4*>(g_x), g);
}

// Scatter into the PERMUTED W' layout (values stay f32; HW truncates those few
// entries at the MMA — negligible vs the tf32 product error).
__global__ void scatter_add_perm_kernel(const float* __restrict__ sw,
                                        const int* __restrict__ rows,
                                        const int* __restrict__ cols, int nnz) {
    int i = blockIdx.x * blockDim.x + threadIdx.x;
    if (i < nnz) {
        int c = cols[i];
        int pc = (c & ~15) | ((c & 3) << 2) | ((c >> 2) & 3);
        atomicAdd(&g_wt[(size_t)rows[i] * K_DIM + pc], sw[i]);
    }
}

// ---------------------------------------------------------------------------
// GEMM: C[M,N] = A @ W'^T + bias
//   mma.sync m16n8k8 tf32, CTA 128x256, warps 2x4 (64x64 each), BK=32,
//   4-stage cp.async pipeline, LDS.128 fragment loads (conflict-free).
// ---------------------------------------------------------------------------
__global__ __launch_bounds__(256, 1)
void gemm_mma_kernel(const float* __restrict__ bias,
                     float* __restrict__ C) {
    extern __shared__ char smem[];
    const uint32_t sb = smem_u32(smem);

    const int tid  = threadIdx.x;
    const int wid  = tid >> 5;
    const int lane = tid & 31;
    const int lq   = lane & 3;      // chunk-in-group / k%4 selector
    const int lr   = lane >> 2;     // 0..7 row-in-fragment

    const int warpM = (wid >> 2) * 64;   // 0 or 64
    const int warpN = (wid & 3) * 64;    // 0,64,128,192

    const int bm = blockIdx.y * BM;
    const int bn = blockIdx.x * BN;

    const float* Ab = g_x + (size_t)bm * K_DIM;
    const float* Bb = g_wt + (size_t)bn * K_DIM;

    // tile loader: thread i copies 16B chunk (r = i>>3, c = i&7);
    // smem chunk index = r*8 + (c ^ PERM(r)); source rows already k-interleaved.
#define LOAD_TILE(t, s)                                                          \
    {                                                                            \
        const uint32_t ab = sb + (s) * A_STAGE_BYTES;                            \
        _Pragma("unroll")                                                        \
        for (int j = 0; j < 4; j++) {                                            \
            int i = tid + j * 256;              /* 0..1023 */                    \
            int r = i >> 3, c = i & 7;                                           \
            uint32_t dst = ab + (uint32_t)(((r << 3) + (c ^ PERM(r))) << 4);     \
            CP_ASYNC16(dst, Ab + (size_t)r * K_DIM + (t) * BK + c * 4);          \
        }                                                                        \
        const uint32_t bb = sb + STAGES * A_STAGE_BYTES + (s) * B_STAGE_BYTES;   \
        _Pragma("unroll")                                                        \
        for (int j = 0; j < 8; j++) {                                            \
            int i = tid + j * 256;              /* 0..2047 */                    \
            int r = i >> 3, c = i & 7;                                           \
            uint32_t dst = bb + (uint32_t)(((r << 3) + (c ^ PERM(r))) << 4);     \
            CP_ASYNC16(dst, Bb + (size_t)r * K_DIM + (t) * BK + c * 4);          \
        }                                                                        \
    }

    // prologue: tiles 0..2 into stages 0..2
#pragma unroll
    for (int p = 0; p < STAGES - 1; p++) {
        LOAD_TILE(p, p);
        CP_COMMIT();
    }

    float acc[4][8][4];
#pragma unroll
    for (int i = 0; i < 4; i++)
#pragma unroll
        for (int j = 0; j < 8; j++)
#pragma unroll
            for (int q = 0; q < 4; q++) acc[i][j][q] = 0.0f;

    for (int t = 0; t < NKT; t++) {
        const int s = t & (STAGES - 1);

        CP_WAIT2();          // tile t resident
        __syncthreads();     // all warps done reading retiring stage

        if (t + STAGES - 1 < NKT) {
            LOAD_TILE(t + STAGES - 1, (t + STAGES - 1) & (STAGES - 1));
        }
        CP_COMMIT();         // empty groups in tail keep the wait count valid

        const uint4* As4 = reinterpret_cast<const uint4*>(smem + s * A_STAGE_BYTES);
        const uint4* Bs4 = reinterpret_cast<const uint4*>(
            smem + STAGES * A_STAGE_BYTES + s * B_STAGE_BYTES);

        // two 16-k groups per tile; each LDS.128 = {k, k+4, k+8, k+12}
#pragma unroll
        for (int g = 0; g < 2; g++) {
            uint4 ua0[4], ua1[4], ub[8];
#pragma unroll
            for (int mt = 0; mt < 4; mt++) {
                const int r0 = warpM + mt * 16 + lr;
                const int r1 = r0 + 8;
                ua0[mt] = As4[(r0 << 3) + ((4 * g + lq) ^ PERM(r0))];
                ua1[mt] = As4[(r1 << 3) + ((4 * g + lq) ^ PERM(r1))];
            }
#pragma unroll
            for (int nt = 0; nt < 8; nt++) {
                const int n = warpN + nt * 8 + lr;
                ub[nt] = Bs4[(n << 3) + ((4 * g + lq) ^ PERM(n))];
            }
            // k-substep 0 (k = 16g .. 16g+7)
#pragma unroll
            for (int mt = 0; mt < 4; mt++)
#pragma unroll
                for (int nt = 0; nt < 8; nt++)
                    mma_tf32(acc[mt][nt][0], acc[mt][nt][1],
                             acc[mt][nt][2], acc[mt][nt][3],
                             ua0[mt].x, ua1[mt].x, ua0[mt].y, ua1[mt].y,
                             ub[nt].x, ub[nt].y);
            // k-substep 1 (k = 16g+8 .. 16g+15)
#pragma unroll
            for (int mt = 0; mt < 4; mt++)
#pragma unroll
                for (int nt = 0; nt < 8; nt++)
                    mma_tf32(acc[mt][nt][0], acc[mt][nt][1],
                             acc[mt][nt][2], acc[mt][nt][3],
                             ua0[mt].z, ua1[mt].z, ua0[mt].w, ua1[mt].w,
                             ub[nt].z, ub[nt].w);
        }
    }

    // Epilogue: bias + store (float2 per fragment row)
#pragma unroll
    for (int nt = 0; nt < 8; nt++) {
        const int col = bn + warpN + nt * 8 + lq * 2;
        const float bv0 = bias[col];
        const float bv1 = bias[col + 1];
#pragma unroll
        for (int mt = 0; mt < 4; mt++) {
            const int r0 = bm + warpM + mt * 16 + lr;
            float2 v0, v1;
            v0.x = acc[mt][nt][0] + bv0;
            v0.y = acc[mt][nt][1] + bv1;
            v1.x = acc[mt][nt][2] + bv0;
            v1.y = acc[mt][nt][3] + bv1;
            *reinterpret_cast<float2*>(&C[(size_t)r0 * N_DIM + col]) = v0;
            *reinterpret_cast<float2*>(&C[(size_t)(r0 + 8) * N_DIM + col]) = v1;
        }
    }
}

// ---------------------------------------------------------------------------
// Launch
// ---------------------------------------------------------------------------
extern "C" void kernel_launch(void* const* d_in, const int* in_sizes, int n_in,
                              void* d_out, int out_size) {
    const float* x    = (const float*)d_in[0];
    const float* w    = (const float*)d_in[1];
    const float* bias = (const float*)d_in[2];
    const float* sw   = (const float*)d_in[3];
    const int*   idx  = (const int*)d_in[4];
    float*       out  = (float*)d_out;
    const int nnz = in_sizes[3];

    // 1) W' = round_tf32(W), k-interleaved
    round_perm_w_kernel<<<(N_DIM * (K_DIM / 16)) / 256, 256>>>(
        reinterpret_cast<const float4*>(w));
    // 2) W' += scatter(sw) at permuted coordinates
    scatter_add_perm_kernel<<<(nnz + 255) / 256, 256>>>(sw, idx, idx + nnz, nnz);
    // 3) x' = round_tf32(x), k-interleaved
    round_perm_x_kernel<<<(int)(((size_t)M_DIM * (K_DIM / 16)) / 256), 256>>>(
        reinterpret_cast<const float4*>(x));

    // 4) GEMM
    cudaFuncSetAttribute(gemm_mma_kernel,
                         cudaFuncAttributeMaxDynamicSharedMemorySize, SMEM_TOTAL);
    dim3 grid(N_DIM / BN, M_DIM / BM);   // (16, 64)
    gemm_mma_kernel<<<grid, 256, SMEM_TOTAL>>>(bias, out);
}